// round 16
// baseline (speedup 1.0000x reference)
#include <cuda_runtime.h>
#include <math.h>

typedef unsigned long long ull;

#define SCALE_F 0.17677669529663687f   // 32^-0.5
#define ATTN_SMEM 59152                // (2048 + 6272 + 6272 + 196) floats

// ---------------- scratch (device globals: allocation-free rule) ----------------
__device__ float g_qpe[64 * 256];       // (q_pos @ Wq) * SCALE
__device__ float g_kpe[196 * 256];      // (k_pos @ Wk)
__device__ float g_Qf[16777216];        // (x @ Wq) * SCALE   [B,H,W,256] head-major ch
__device__ float g_Kf[16777216];        // x @ Wk
__device__ float g_Vf[16777216];        // x @ Wv
__device__ float g_AO[16777216];        // attention output, head-major channels

// ---------------- packed fp32x2 helpers (Blackwell dual-FP32 pipe) --------------
__device__ __forceinline__ ull ffma2(ull a, ull b, ull c) {
    ull d;
    asm("fma.rn.f32x2 %0, %1, %2, %3;" : "=l"(d) : "l"(a), "l"(b), "l"(c));
    return d;
}
__device__ __forceinline__ ull pk2(float x, float y) {
    ull r;
    asm("mov.b64 %0, {%1, %2};" : "=l"(r) : "f"(x), "f"(y));
    return r;
}
__device__ __forceinline__ float2 upk2(ull v) {
    float2 r;
    asm("mov.b64 {%0, %1}, %2;" : "=f"(r.x), "=f"(r.y) : "l"(v));
    return r;
}

// ---------------- position-embedding projection (qpe, kpe) ----------------------
// 260 blocks: r<64 -> q_pos row r; else k_pos row r-64. 256 threads = out channel.
__global__ void pe_kernel(const float* __restrict__ Wq, const float* __restrict__ Wk) {
    __shared__ float pos[256];
    const int r = blockIdx.x;
    const bool isq = (r < 64);
    int i, j;
    if (isq) { i = 3 + (r >> 3); j = 3 + (r & 7); }
    else     { int rr = r - 64; i = rr / 14; j = rr % 14; }
    const int c = threadIdx.x;
    const int cc = c & 127;
    float base = (c < 128) ? (float)(i + 1) : (float)(j + 1);
    float e = base * (6.283185307179586f / (14.0f + 1e-6f));
    float t = powf(10000.0f, (float)(cc & ~1) * (1.0f / 128.0f));
    float ph = e / t;
    pos[c] = (cc & 1) ? cosf(ph) : sinf(ph);
    __syncthreads();
    const float* W = isq ? Wq : Wk;
    float acc = 0.0f;
    for (int k = 0; k < 256; k++) acc = fmaf(pos[k], W[(k << 8) + c], acc);
    if (isq) g_qpe[(r << 8) + c] = acc * SCALE_F;
    else     g_kpe[((r - 64) << 8) + c] = acc;
}

// ---------------- 128x128x256 fp32x2 SGEMM tile (K fixed = 256, W ld = 256) ------
__device__ __forceinline__ void sgemm_tile(const float* __restrict__ A,
                                           const float* __restrict__ W,
                                           float* __restrict__ Out,
                                           int m0, int c0, float sc,
                                           const float* __restrict__ bias) {
    __shared__ __align__(16) float As[16][132];   // [k][m], 528B rows (16B multiple)
    __shared__ __align__(16) float Bs[16][128];   // [k][n]
    const int tid = threadIdx.x;
    const int tx = tid & 15, ty = tid >> 4;
    const int ar = tid >> 2;             // A-load row group (0..63)
    const int af = (tid & 3) << 2;       // A-load k offset {0,4,8,12}

    ull acc[4][8];                       // 4 m-pairs (8 rows) x 8 cols
#pragma unroll
    for (int i = 0; i < 4; i++)
#pragma unroll
        for (int jj = 0; jj < 8; jj++) acc[i][jj] = 0ull;

    for (int kt = 0; kt < 256; kt += 16) {
#pragma unroll
        for (int rr = 0; rr < 2; rr++) {
            int r = ar + (rr << 6);
            float4 v = *(const float4*)&A[(m0 + r) * 256 + kt + af];
            As[af + 0][r] = v.x; As[af + 1][r] = v.y;
            As[af + 2][r] = v.z; As[af + 3][r] = v.w;
        }
#pragma unroll
        for (int rr = 0; rr < 2; rr++) {
            int idx = tid + (rr << 8);
            int k = idx >> 5, ccol = (idx & 31) << 2;
            *(float4*)&Bs[k][ccol] = *(const float4*)&W[(kt + k) * 256 + c0 + ccol];
        }
        __syncthreads();
#pragma unroll
        for (int kk = 0; kk < 16; kk++) {
            ulonglong2 a01 = *(const ulonglong2*)&As[kk][ty << 3];
            ulonglong2 a23 = *(const ulonglong2*)&As[kk][(ty << 3) + 4];
            float4 b0 = *(const float4*)&Bs[kk][tx << 3];
            float4 b1 = *(const float4*)&Bs[kk][(tx << 3) + 4];
            ull a[4] = {a01.x, a01.y, a23.x, a23.y};
            ull bs[8] = {pk2(b0.x, b0.x), pk2(b0.y, b0.y), pk2(b0.z, b0.z), pk2(b0.w, b0.w),
                         pk2(b1.x, b1.x), pk2(b1.y, b1.y), pk2(b1.z, b1.z), pk2(b1.w, b1.w)};
#pragma unroll
            for (int i = 0; i < 4; i++)
#pragma unroll
                for (int jj = 0; jj < 8; jj++)
                    acc[i][jj] = ffma2(a[i], bs[jj], acc[i][jj]);
        }
        __syncthreads();
    }

    const int cbase = c0 + (tx << 3);
    float4 bd0 = make_float4(0.f, 0.f, 0.f, 0.f), bd1 = bd0;
    if (bias) {
        bd0 = *(const float4*)&bias[cbase];
        bd1 = *(const float4*)&bias[cbase + 4];
    }
#pragma unroll
    for (int i = 0; i < 4; i++) {
        float2 u[8];
#pragma unroll
        for (int jj = 0; jj < 8; jj++) u[jj] = upk2(acc[i][jj]);
        int m = m0 + (ty << 3) + (i << 1);
        float4 r0a = make_float4(fmaf(u[0].x, sc, bd0.x), fmaf(u[1].x, sc, bd0.y),
                                 fmaf(u[2].x, sc, bd0.z), fmaf(u[3].x, sc, bd0.w));
        float4 r0b = make_float4(fmaf(u[4].x, sc, bd1.x), fmaf(u[5].x, sc, bd1.y),
                                 fmaf(u[6].x, sc, bd1.z), fmaf(u[7].x, sc, bd1.w));
        float4 r1a = make_float4(fmaf(u[0].y, sc, bd0.x), fmaf(u[1].y, sc, bd0.y),
                                 fmaf(u[2].y, sc, bd0.z), fmaf(u[3].y, sc, bd0.w));
        float4 r1b = make_float4(fmaf(u[4].y, sc, bd1.x), fmaf(u[5].y, sc, bd1.y),
                                 fmaf(u[6].y, sc, bd1.z), fmaf(u[7].y, sc, bd1.w));
        *(float4*)&Out[m * 256 + cbase]           = r0a;
        *(float4*)&Out[m * 256 + cbase + 4]       = r0b;
        *(float4*)&Out[(m + 1) * 256 + cbase]     = r1a;
        *(float4*)&Out[(m + 1) * 256 + cbase + 4] = r1b;
    }
}

// grid (512, 6): y 0,1 -> Q halves; 2,3 -> K; 4,5 -> V
__global__ __launch_bounds__(256, 2) void gemm_qkv(const float* __restrict__ X,
                                                   const float* __restrict__ Wq,
                                                   const float* __restrict__ Wk,
                                                   const float* __restrict__ Wv) {
    const int bn = blockIdx.y;
    const int mat = bn >> 1;
    const int c0 = (bn & 1) << 7;
    const float* W = (mat == 0) ? Wq : (mat == 1) ? Wk : Wv;
    float* Out = (mat == 0) ? g_Qf : (mat == 1) ? g_Kf : g_Vf;
    const float sc = (mat == 0) ? SCALE_F : 1.0f;
    sgemm_tile(X, W, Out, blockIdx.x << 7, c0, sc, nullptr);
}

// grid (512, 2): out = AO @ Wproj + bproj
__global__ __launch_bounds__(256, 2) void gemm_proj(const float* __restrict__ Wp,
                                                    const float* __restrict__ bias,
                                                    float* __restrict__ Out) {
    sgemm_tile(g_AO, Wp, Out, blockIdx.x << 7, blockIdx.y << 7, 1.0f, bias);
}

// ---------------- halo attention: CTA = (head, block, batch), 64 lanes = q rows --
__global__ __launch_bounds__(64) void attn_kernel() {
    extern __shared__ __align__(16) float smem[];
    float* q_sm = smem;              // 64 x 32
    float* k_sm = smem + 2048;       // 196 x 32
    float* v_sm = k_sm + 6272;       // 196 x 32
    float* msk  = v_sm + 6272;       // 196 (0 or -1e30)

    const int h = blockIdx.x;
    const int nbk = blockIdx.y;
    const int b = blockIdx.z;
    const int by = nbk >> 4, bx = nbk & 15;
    const int tid = threadIdx.x;
    const int ch0 = h << 5;
    const int pixbase = b << 14;     // b * 128*128

    // stage Q (+qpe, already scaled)
#pragma unroll
    for (int i = 0; i < 8; i++) {
        int idx = tid + (i << 6);
        int r = idx >> 3, c4 = (idx & 7) << 2;
        int py = (by << 3) + (r >> 3);
        int px = (bx << 3) + (r & 7);
        int off = ((pixbase + (py << 7) + px) << 8) + ch0 + c4;
        float4 qv = *(const float4*)&g_Qf[off];
        float4 pe = *(const float4*)&g_qpe[(r << 8) + ch0 + c4];
        qv.x += pe.x; qv.y += pe.y; qv.z += pe.z; qv.w += pe.w;
        *(float4*)&q_sm[(r << 5) + c4] = qv;
    }
    // stage K (+kpe) / V halo window with validity mask
    for (int idx = tid; idx < 1568; idx += 64) {
        int j = idx >> 3, c4 = (idx & 7) << 2;
        int wy = j / 14, wx = j - wy * 14;
        int py = (by << 3) - 3 + wy;
        int px = (bx << 3) - 3 + wx;
        bool valid = ((unsigned)py < 128u) && ((unsigned)px < 128u);
        float4 kv = make_float4(0.f, 0.f, 0.f, 0.f);
        float4 vv = kv;
        if (valid) {
            int off = ((pixbase + (py << 7) + px) << 8) + ch0 + c4;
            kv = *(const float4*)&g_Kf[off];
            float4 pe = *(const float4*)&g_kpe[(j << 8) + ch0 + c4];
            kv.x += pe.x; kv.y += pe.y; kv.z += pe.z; kv.w += pe.w;
            vv = *(const float4*)&g_Vf[off];
        }
        *(float4*)&k_sm[(j << 5) + c4] = kv;
        *(float4*)&v_sm[(j << 5) + c4] = vv;
        if (c4 == 0) msk[j] = valid ? 0.0f : -1e30f;
    }
    __syncthreads();

    // per-lane: q row in regs (packed), stream k/v rows via smem broadcast
    ull q2[16], o2[16];
    {
        const ulonglong2* qp = (const ulonglong2*)&q_sm[tid << 5];
#pragma unroll
        for (int u = 0; u < 8; u++) {
            ulonglong2 tq = qp[u];
            q2[2 * u] = tq.x; q2[2 * u + 1] = tq.y;
        }
    }
#pragma unroll
    for (int u = 0; u < 16; u++) o2[u] = 0ull;
    float l = 0.0f;

#pragma unroll 2
    for (int j = 0; j < 196; j++) {
        const ulonglong2* kp = (const ulonglong2*)&k_sm[j << 5];
        ull a0 = 0ull, a1 = 0ull, a2 = 0ull, a3 = 0ull;
#pragma unroll
        for (int u = 0; u < 4; u++) {
            ulonglong2 k01 = kp[2 * u];
            ulonglong2 k23 = kp[2 * u + 1];
            a0 = ffma2(q2[4 * u + 0], k01.x, a0);
            a1 = ffma2(q2[4 * u + 1], k01.y, a1);
            a2 = ffma2(q2[4 * u + 2], k23.x, a2);
            a3 = ffma2(q2[4 * u + 3], k23.y, a3);
        }
        float2 f0 = upk2(a0), f1 = upk2(a1), f2 = upk2(a2), f3 = upk2(a3);
        float s = ((f0.x + f0.y) + (f1.x + f1.y)) + ((f2.x + f2.y) + (f3.x + f3.y)) + msk[j];
        // scores O(1) (q pre-scaled): exp cannot overflow; masked -> exp(-1e30)=0
        float p = __expf(s);
        l += p;
        ull p2 = pk2(p, p);
        const ulonglong2* vp = (const ulonglong2*)&v_sm[j << 5];
#pragma unroll
        for (int u = 0; u < 8; u++) {
            ulonglong2 vq = vp[u];
            o2[2 * u]     = ffma2(p2, vq.x, o2[2 * u]);
            o2[2 * u + 1] = ffma2(p2, vq.y, o2[2 * u + 1]);
        }
    }
    float inv = 1.0f / l;
    int py = (by << 3) + (tid >> 3);
    int px = (bx << 3) + (tid & 7);
    float* op = &g_AO[((pixbase + (py << 7) + px) << 8) + ch0];
#pragma unroll
    for (int u = 0; u < 8; u++) {
        float2 e0 = upk2(o2[2 * u]);
        float2 e1 = upk2(o2[2 * u + 1]);
        *(float4*)&op[u << 2] = make_float4(e0.x * inv, e0.y * inv, e1.x * inv, e1.y * inv);
    }
}

// ---------------- launch ---------------------------------------------------------
extern "C" void kernel_launch(void* const* d_in, const int* in_sizes, int n_in,
                              void* d_out, int out_size) {
    const float* x  = (const float*)d_in[0];
    const float* Wq = (const float*)d_in[1];
    const float* Wk = (const float*)d_in[2];
    const float* Wv = (const float*)d_in[3];
    const float* Wp = (const float*)d_in[4];
    const float* bp = (const float*)d_in[5];
    float* out = (float*)d_out;

    cudaFuncSetAttribute(attn_kernel, cudaFuncAttributeMaxDynamicSharedMemorySize, ATTN_SMEM);

    pe_kernel<<<260, 256>>>(Wq, Wk);
    gemm_qkv<<<dim3(512, 6), 256>>>(x, Wq, Wk, Wv);
    attn_kernel<<<dim3(8, 256, 4), 64, ATTN_SMEM>>>();
    gemm_proj<<<dim3(512, 2), 256>>>(Wp, bp, out);
}

// round 17
// speedup vs baseline: 1.2196x; 1.2196x over previous
#include <cuda_runtime.h>
#include <math.h>

typedef unsigned long long ull;

#define SCALE_F 0.17677669529663687f   // 32^-0.5
#define ATTN_SMEM (2 * 12740 * 4)      // two heads x (196*32 K + 196*32 V + 196 msk) floats

// ---------------- scratch (device globals: allocation-free rule) ----------------
__device__ float g_qpe[64 * 256];       // (q_pos @ Wq) * SCALE
__device__ float g_kpe[196 * 256];      // (k_pos @ Wk)
__device__ float g_Qf[16777216];        // (x @ Wq) * SCALE   [B,H,W,256]
__device__ float g_Kf[16777216];        // x @ Wk
__device__ float g_Vf[16777216];        // x @ Wv
__device__ float g_AO[16777216];        // attention output

// ---------------- packed fp32x2 helpers (Blackwell dual-FP32 pipe) --------------
__device__ __forceinline__ ull ffma2(ull a, ull b, ull c) {
    ull d;
    asm("fma.rn.f32x2 %0, %1, %2, %3;" : "=l"(d) : "l"(a), "l"(b), "l"(c));
    return d;
}
__device__ __forceinline__ ull pk2(float x, float y) {
    ull r;
    asm("mov.b64 %0, {%1, %2};" : "=l"(r) : "f"(x), "f"(y));
    return r;
}
__device__ __forceinline__ float2 upk2(ull v) {
    float2 r;
    asm("mov.b64 {%0, %1}, %2;" : "=f"(r.x), "=f"(r.y) : "l"(v));
    return r;
}

// ---------------- position-embedding projection (qpe, kpe) ----------------------
__global__ void pe_kernel(const float* __restrict__ Wq, const float* __restrict__ Wk) {
    __shared__ float pos[256];
    const int r = blockIdx.x;
    const bool isq = (r < 64);
    int i, j;
    if (isq) { i = 3 + (r >> 3); j = 3 + (r & 7); }
    else     { int rr = r - 64; i = rr / 14; j = rr % 14; }
    const int c = threadIdx.x;
    const int cc = c & 127;
    float base = (c < 128) ? (float)(i + 1) : (float)(j + 1);
    float e = base * (6.283185307179586f / (14.0f + 1e-6f));
    float t = powf(10000.0f, (float)(cc & ~1) * (1.0f / 128.0f));
    float ph = e / t;
    pos[c] = (cc & 1) ? cosf(ph) : sinf(ph);
    __syncthreads();
    const float* W = isq ? Wq : Wk;
    float acc = 0.0f;
    for (int k = 0; k < 256; k++) acc = fmaf(pos[k], W[(k << 8) + c], acc);
    if (isq) g_qpe[(r << 8) + c] = acc * SCALE_F;
    else     g_kpe[((r - 64) << 8) + c] = acc;
}

// ------- 128x128x256 fp32x2 SGEMM tile: double-buffered, conflict-remapped B ----
__device__ __forceinline__ void sgemm_tile(const float* __restrict__ A,
                                           const float* __restrict__ W,
                                           float* __restrict__ Out,
                                           int m0, int c0, float sc,
                                           const float* __restrict__ bias) {
    __shared__ __align__(16) float As[2][16][132];   // [stage][k][m]
    __shared__ __align__(16) float Bs[2][16][128];   // [stage][k][n]
    const int tid = threadIdx.x;
    const int tx = tid & 15, ty = tid >> 4;
    const int ar = tid >> 2;             // A-load row (0..63)
    const int af = (tid & 3) << 2;       // A-load k offset {0,4,8,12}
    const int bk = tid >> 5;             // B-load k row base (0..7)
    const int bc = (tid & 31) << 2;      // B-load col (0..124)

    ull acc[4][8];
#pragma unroll
    for (int i = 0; i < 4; i++)
#pragma unroll
        for (int jj = 0; jj < 8; jj++) acc[i][jj] = 0ull;

    float4 a_reg[2], b_reg[2];
    // preload k-tile 0
#pragma unroll
    for (int rr = 0; rr < 2; rr++)
        a_reg[rr] = *(const float4*)&A[(m0 + ar + (rr << 6)) * 256 + af];
#pragma unroll
    for (int rr = 0; rr < 2; rr++)
        b_reg[rr] = *(const float4*)&W[(bk + (rr << 3)) * 256 + c0 + bc];
#pragma unroll
    for (int rr = 0; rr < 2; rr++) {
        int r = ar + (rr << 6);
        As[0][af + 0][r] = a_reg[rr].x; As[0][af + 1][r] = a_reg[rr].y;
        As[0][af + 2][r] = a_reg[rr].z; As[0][af + 3][r] = a_reg[rr].w;
        *(float4*)&Bs[0][bk + (rr << 3)][bc] = b_reg[rr];
    }
    __syncthreads();

    for (int kt = 0; kt < 256; kt += 16) {
        const int cur = (kt >> 4) & 1;
        const bool more = (kt + 16) < 256;
        if (more) {
#pragma unroll
            for (int rr = 0; rr < 2; rr++)
                a_reg[rr] = *(const float4*)&A[(m0 + ar + (rr << 6)) * 256 + kt + 16 + af];
#pragma unroll
            for (int rr = 0; rr < 2; rr++)
                b_reg[rr] = *(const float4*)&W[(kt + 16 + bk + (rr << 3)) * 256 + c0 + bc];
        }
#pragma unroll
        for (int kk = 0; kk < 16; kk++) {
            ulonglong2 a01 = *(const ulonglong2*)&As[cur][kk][ty << 3];
            ulonglong2 a23 = *(const ulonglong2*)&As[cur][kk][(ty << 3) + 4];
            // conflict-remapped B: this thread owns cols [tx*4..+3] and [64+tx*4..+3]
            float4 b0 = *(const float4*)&Bs[cur][kk][tx << 2];
            float4 b1 = *(const float4*)&Bs[cur][kk][64 + (tx << 2)];
            ull a[4] = {a01.x, a01.y, a23.x, a23.y};
            ull bs[8] = {pk2(b0.x, b0.x), pk2(b0.y, b0.y), pk2(b0.z, b0.z), pk2(b0.w, b0.w),
                         pk2(b1.x, b1.x), pk2(b1.y, b1.y), pk2(b1.z, b1.z), pk2(b1.w, b1.w)};
#pragma unroll
            for (int i = 0; i < 4; i++)
#pragma unroll
                for (int jj = 0; jj < 8; jj++)
                    acc[i][jj] = ffma2(a[i], bs[jj], acc[i][jj]);
        }
        if (more) {
            const int nxt = cur ^ 1;
#pragma unroll
            for (int rr = 0; rr < 2; rr++) {
                int r = ar + (rr << 6);
                As[nxt][af + 0][r] = a_reg[rr].x; As[nxt][af + 1][r] = a_reg[rr].y;
                As[nxt][af + 2][r] = a_reg[rr].z; As[nxt][af + 3][r] = a_reg[rr].w;
                *(float4*)&Bs[nxt][bk + (rr << 3)][bc] = b_reg[rr];
            }
        }
        __syncthreads();
    }

    const int cb0 = c0 + (tx << 2);
    const int cb1 = cb0 + 64;
    float4 bd0 = make_float4(0.f, 0.f, 0.f, 0.f), bd1 = bd0;
    if (bias) {
        bd0 = *(const float4*)&bias[cb0];
        bd1 = *(const float4*)&bias[cb1];
    }
#pragma unroll
    for (int i = 0; i < 4; i++) {
        float2 u[8];
#pragma unroll
        for (int jj = 0; jj < 8; jj++) u[jj] = upk2(acc[i][jj]);
        int m = m0 + (ty << 3) + (i << 1);
        *(float4*)&Out[m * 256 + cb0] =
            make_float4(fmaf(u[0].x, sc, bd0.x), fmaf(u[1].x, sc, bd0.y),
                        fmaf(u[2].x, sc, bd0.z), fmaf(u[3].x, sc, bd0.w));
        *(float4*)&Out[m * 256 + cb1] =
            make_float4(fmaf(u[4].x, sc, bd1.x), fmaf(u[5].x, sc, bd1.y),
                        fmaf(u[6].x, sc, bd1.z), fmaf(u[7].x, sc, bd1.w));
        *(float4*)&Out[(m + 1) * 256 + cb0] =
            make_float4(fmaf(u[0].y, sc, bd0.x), fmaf(u[1].y, sc, bd0.y),
                        fmaf(u[2].y, sc, bd0.z), fmaf(u[3].y, sc, bd0.w));
        *(float4*)&Out[(m + 1) * 256 + cb1] =
            make_float4(fmaf(u[4].y, sc, bd1.x), fmaf(u[5].y, sc, bd1.y),
                        fmaf(u[6].y, sc, bd1.z), fmaf(u[7].y, sc, bd1.w));
    }
}

// grid (512, 6): y 0,1 -> Q halves; 2,3 -> K; 4,5 -> V
__global__ __launch_bounds__(256, 2) void gemm_qkv(const float* __restrict__ X,
                                                   const float* __restrict__ Wq,
                                                   const float* __restrict__ Wk,
                                                   const float* __restrict__ Wv) {
    const int bn = blockIdx.y;
    const int mat = bn >> 1;
    const int c0 = (bn & 1) << 7;
    const float* W = (mat == 0) ? Wq : (mat == 1) ? Wk : Wv;
    float* Out = (mat == 0) ? g_Qf : (mat == 1) ? g_Kf : g_Vf;
    const float sc = (mat == 0) ? SCALE_F : 1.0f;
    sgemm_tile(X, W, Out, blockIdx.x << 7, c0, sc, nullptr);
}

// grid (512, 2): out = AO @ Wproj + bproj
__global__ __launch_bounds__(256, 2) void gemm_proj(const float* __restrict__ Wp,
                                                    const float* __restrict__ bias,
                                                    float* __restrict__ Out) {
    sgemm_tile(g_AO, Wp, Out, blockIdx.x << 7, blockIdx.y << 7, 1.0f, bias);
}

// ------- halo attention: CTA = (head PAIR, block, batch), 128 threads -----------
// warps 0,1 -> head 2h (SMSP 0,1); warps 2,3 -> head 2h+1 (SMSP 2,3)
__global__ __launch_bounds__(128) void attn_kernel() {
    extern __shared__ __align__(16) float smem[];
    const int half = threadIdx.x >> 6;     // which head of the pair
    const int tid = threadIdx.x & 63;      // q row within block
    const int h = (blockIdx.x << 1) + half;
    const int nbk = blockIdx.y;
    const int b = blockIdx.z;
    const int by = nbk >> 4, bx = nbk & 15;
    const int ch0 = h << 5;
    const int pixbase = b << 14;

    float* k_sm = smem + half * 12740;     // 196 x 32
    float* v_sm = k_sm + 6272;             // 196 x 32
    float* msk  = v_sm + 6272;             // 196

    // stage K (+kpe) / V halo window with validity mask (64 threads per half)
    for (int idx = tid; idx < 1568; idx += 64) {
        int j = idx >> 3, c4 = (idx & 7) << 2;
        int wy = j / 14, wx = j - wy * 14;
        int py = (by << 3) - 3 + wy;
        int px = (bx << 3) - 3 + wx;
        bool valid = ((unsigned)py < 128u) && ((unsigned)px < 128u);
        float4 kv = make_float4(0.f, 0.f, 0.f, 0.f);
        float4 vv = kv;
        if (valid) {
            int off = ((pixbase + (py << 7) + px) << 8) + ch0 + c4;
            kv = *(const float4*)&g_Kf[off];
            float4 pe = *(const float4*)&g_kpe[(j << 8) + ch0 + c4];
            kv.x += pe.x; kv.y += pe.y; kv.z += pe.z; kv.w += pe.w;
            vv = *(const float4*)&g_Vf[off];
        }
        *(float4*)&k_sm[(j << 5) + c4] = kv;
        *(float4*)&v_sm[(j << 5) + c4] = vv;
        if ((idx & 7) == 0) msk[j] = valid ? 0.0f : -1e30f;
    }

    // Q (+qpe, pre-scaled) straight from global into packed registers
    ull q2[16], o2[16];
    {
        int py = (by << 3) + (tid >> 3);
        int px = (bx << 3) + (tid & 7);
        const float4* qp = (const float4*)&g_Qf[((pixbase + (py << 7) + px) << 8) + ch0];
        const float4* pp = (const float4*)&g_qpe[(tid << 8) + ch0];
#pragma unroll
        for (int u = 0; u < 8; u++) {
            float4 qv = qp[u], pe = pp[u];
            q2[2 * u]     = pk2(qv.x + pe.x, qv.y + pe.y);
            q2[2 * u + 1] = pk2(qv.z + pe.z, qv.w + pe.w);
        }
    }
#pragma unroll
    for (int u = 0; u < 16; u++) o2[u] = 0ull;
    float l = 0.0f;
    __syncthreads();

#pragma unroll 2
    for (int j = 0; j < 196; j++) {
        const ulonglong2* kp = (const ulonglong2*)&k_sm[j << 5];
        ull a0 = 0ull, a1 = 0ull, a2 = 0ull, a3 = 0ull;
#pragma unroll
        for (int u = 0; u < 4; u++) {
            ulonglong2 k01 = kp[2 * u];
            ulonglong2 k23 = kp[2 * u + 1];
            a0 = ffma2(q2[4 * u + 0], k01.x, a0);
            a1 = ffma2(q2[4 * u + 1], k01.y, a1);
            a2 = ffma2(q2[4 * u + 2], k23.x, a2);
            a3 = ffma2(q2[4 * u + 3], k23.y, a3);
        }
        float2 f0 = upk2(a0), f1 = upk2(a1), f2 = upk2(a2), f3 = upk2(a3);
        float s = ((f0.x + f0.y) + (f1.x + f1.y)) + ((f2.x + f2.y) + (f3.x + f3.y)) + msk[j];
        // scores O(1) (q pre-scaled): exp cannot overflow; masked -> exp(-1e30)=0
        float p = __expf(s);
        l += p;
        ull p2 = pk2(p, p);
        const ulonglong2* vp = (const ulonglong2*)&v_sm[j << 5];
#pragma unroll
        for (int u = 0; u < 8; u++) {
            ulonglong2 vq = vp[u];
            o2[2 * u]     = ffma2(p2, vq.x, o2[2 * u]);
            o2[2 * u + 1] = ffma2(p2, vq.y, o2[2 * u + 1]);
        }
    }
    float inv = 1.0f / l;
    int py = (by << 3) + (tid >> 3);
    int px = (bx << 3) + (tid & 7);
    float* op = &g_AO[((pixbase + (py << 7) + px) << 8) + ch0];
#pragma unroll
    for (int u = 0; u < 8; u++) {
        float2 e0 = upk2(o2[2 * u]);
        float2 e1 = upk2(o2[2 * u + 1]);
        *(float4*)&op[u << 2] = make_float4(e0.x * inv, e0.y * inv, e1.x * inv, e1.y * inv);
    }
}

// ---------------- launch ---------------------------------------------------------
extern "C" void kernel_launch(void* const* d_in, const int* in_sizes, int n_in,
                              void* d_out, int out_size) {
    const float* x  = (const float*)d_in[0];
    const float* Wq = (const float*)d_in[1];
    const float* Wk = (const float*)d_in[2];
    const float* Wv = (const float*)d_in[3];
    const float* Wp = (const float*)d_in[4];
    const float* bp = (const float*)d_in[5];
    float* out = (float*)d_out;

    cudaFuncSetAttribute(attn_kernel, cudaFuncAttributeMaxDynamicSharedMemorySize, ATTN_SMEM);

    pe_kernel<<<260, 256>>>(Wq, Wk);
    gemm_qkv<<<dim3(512, 6), 256>>>(x, Wq, Wk, Wv);
    attn_kernel<<<dim3(4, 256, 4), 128, ATTN_SMEM>>>();
    gemm_proj<<<dim3(512, 2), 256>>>(Wp, bp, out);
}